// round 11
// baseline (speedup 1.0000x reference)
#include <cuda_runtime.h>
#include <cuda_fp16.h>
#include <cstdint>

#define NN 8192
#define DD 128
#define K2C 20.6099286f    // 1/(0.07*ln2)

#define NTILE 64
#define GS 4                               // tiles per column group
#define NGROUP 544                         // sum over rt of ceil((64-rt)/4)
#define SMEM_BYTES 98304                   // A | B0 | B1, 32KB each

// ---------------------------------------------------------------------------
__device__ uint32_t g_h[NN * 64];    // normalized feats, fp16x2
__device__ float    g_rowsum[NN];
__device__ float    g_pos[NN];
__device__ int      g_done;

__device__ __forceinline__ uint32_t smem_u32(const void* p) {
    uint32_t a;
    asm("{ .reg .u64 t; cvta.to.shared.u64 t, %1; cvt.u32.u64 %0, t; }" : "=r"(a) : "l"(p));
    return a;
}
__device__ __forceinline__ float ex2f(float x) {
    float y; asm("ex2.approx.ftz.f32 %0, %1;" : "=f"(y) : "f"(x)); return y;
}
__device__ __forceinline__ float lg2f(float x) {
    float y; asm("lg2.approx.f32 %0, %1;" : "=f"(y) : "f"(x)); return y;
}
__device__ __forceinline__ void cp16(uint32_t dst, const void* src) {
    asm volatile("cp.async.cg.shared.global [%0], [%1], 16;" :: "r"(dst), "l"(src));
}
#define CP_COMMIT() asm volatile("cp.async.commit_group;" ::: "memory")
#define CP_WAIT(n)  asm volatile("cp.async.wait_group %0;" :: "n"(n) : "memory")

#define LDSM4(r0, r1, r2, r3, a) \
    asm volatile("ldmatrix.sync.aligned.m8n8.x4.shared.b16 {%0,%1,%2,%3}, [%4];" \
                 : "=r"(r0), "=r"(r1), "=r"(r2), "=r"(r3) : "r"(a))
#define MMA16816(d, a, b0v, b1v) \
    asm volatile("mma.sync.aligned.m16n8k16.row.col.f32.f16.f16.f32 " \
                 "{%0,%1,%2,%3},{%4,%5,%6,%7},{%8,%9},{%0,%1,%2,%3};" \
                 : "+f"((d)[0]), "+f"((d)[1]), "+f"((d)[2]), "+f"((d)[3]) \
                 : "r"((a)[0]), "r"((a)[1]), "r"((a)[2]), "r"((a)[3]), \
                   "r"(b0v), "r"(b1v))

// ---------------------------------------------------------------------------
// Kernel 1: row L2-normalize -> fp16 (round-3 version: warp per row)
// ---------------------------------------------------------------------------
__global__ void norm_kernel(const float* __restrict__ feats) {
    int row  = blockIdx.x * 8 + (threadIdx.x >> 5);
    int lane = threadIdx.x & 31;
    float4 v = ((const float4*)(feats + (size_t)row * DD))[lane];
    float ss = v.x * v.x + v.y * v.y + v.z * v.z + v.w * v.w;
    #pragma unroll
    for (int o = 16; o; o >>= 1) ss += __shfl_xor_sync(0xffffffffu, ss, o);
    float inv = 1.0f / fmaxf(sqrtf(ss), 1e-8f);
    __half2 p0 = __floats2half2_rn(v.x * inv, v.y * inv);
    __half2 p1 = __floats2half2_rn(v.z * inv, v.w * inv);
    uint2 pk;
    pk.x = *(uint32_t*)&p0;
    pk.y = *(uint32_t*)&p1;
    *(uint2*)(g_h + (size_t)row * 64 + lane * 2) = pk;
    if (lane == 0) g_rowsum[row] = 0.0f;
}

// ---------------------------------------------------------------------------
// Kernel 2: occ-1, A fragments register-resident, 4-tile groups, fused finish
// ---------------------------------------------------------------------------
__device__ __forceinline__ void copy_tile_async(uint32_t smemBase,
                                                const uint4* __restrict__ src,
                                                int tid) {
    #pragma unroll
    for (int i = 0; i < 8; i++) {
        int idx = tid + i * 256;
        int r = idx >> 4, c = idx & 15;
        cp16(smemBase + (uint32_t)((r * 16 + (c ^ (r & 7))) << 4), src + idx);
    }
}

__global__ void __launch_bounds__(256, 1) sim_kernel(float* __restrict__ out) {
    extern __shared__ uint4 sm4[];
    __shared__ float red[256];
    __shared__ int lastFlag;

    const int tid  = threadIdx.x;
    const int lane = tid & 31;
    const int wid  = tid >> 5;

    // decode bid -> (rt, quad); groups(rt) = ceil((64-rt)/4)
    int rt = 0, cum = 0;
    {
        const int bid = blockIdx.x;
        while (cum + ((NTILE - rt + GS - 1) >> 2) <= bid) {
            cum += (NTILE - rt + GS - 1) >> 2;
            rt++;
        }
    }
    const int quad = (int)blockIdx.x - cum;
    const int ct0  = rt + quad * GS;
    int ntiles = NTILE - ct0;
    if (ntiles > GS) ntiles = GS;
    const int rowBase = rt * 128;

    const uint32_t smA  = smem_u32(sm4);
    const uint32_t smB0 = smA + 32768;
    const uint32_t smB1 = smA + 65536;

    // prologue: A + B(ct0) group0 ; B(ct0+1) group1
    copy_tile_async(smA,  (const uint4*)g_h + (size_t)rowBase * 16, tid);
    copy_tile_async(smB0, (const uint4*)g_h + (size_t)(ct0 * 128) * 16, tid);
    CP_COMMIT();
    if (ntiles > 1) {
        copy_tile_async(smB1, (const uint4*)g_h + (size_t)((ct0 + 1) * 128) * 16, tid);
        CP_COMMIT();
        CP_WAIT(1);
    } else {
        CP_WAIT(0);
    }
    __syncthreads();

    const int warpM = wid & 1;
    const int warpN = wid >> 1;
    const int aRowL = warpM * 64 + (lane & 15);
    const int aCB   = lane >> 4;
    const int bRowL = warpN * 32 + ((lane & 7) | ((lane >> 1) & 8));
    const int bCB   = (lane >> 3) & 1;
    const int rBase0 = rowBase + warpM * 64 + (lane >> 2);
    const int cOffW  = warpN * 32 + (lane & 3) * 2;

    // A fragments: register-resident for the whole group (128 regs, occ-1 ok)
    uint32_t afr[8][4][4];
    #pragma unroll
    for (int ks = 0; ks < 8; ks++)
        #pragma unroll
        for (int mi = 0; mi < 4; mi++) {
            int r = aRowL + mi * 16;
            int ch = 2 * ks + aCB;
            LDSM4(afr[ks][mi][0], afr[ks][mi][1], afr[ks][mi][2], afr[ks][mi][3],
                  smA + r * 256 + ((ch ^ (r & 7)) << 4));
        }

    float racc[4][2];
    #pragma unroll
    for (int u = 0; u < 4; u++) { racc[u][0] = 0.0f; racc[u][1] = 0.0f; }

    for (int t = 0; t < ntiles; t++) {
        const int ct = ct0 + t;
        const int colBase = ct * 128;
        const bool isDiag = (ct == rt);
        const bool hasPos = (ct == rt + 32);
        const uint32_t smB = (t & 1) ? smB1 : smB0;

        float C[4][4][4];
        #pragma unroll
        for (int mi = 0; mi < 4; mi++)
            #pragma unroll
            for (int nj = 0; nj < 4; nj++)
                #pragma unroll
                for (int q = 0; q < 4; q++) C[mi][nj][q] = 0.0f;

        #pragma unroll
        for (int ks = 0; ks < 8; ks++) {
            uint32_t b[2][4];
            #pragma unroll
            for (int nh = 0; nh < 2; nh++) {
                int r = bRowL + nh * 16;
                int ch = 2 * ks + bCB;
                LDSM4(b[nh][0], b[nh][1], b[nh][2], b[nh][3],
                      smB + r * 256 + ((ch ^ (r & 7)) << 4));
            }
            #pragma unroll
            for (int mi = 0; mi < 4; mi++)
                #pragma unroll
                for (int nj = 0; nj < 4; nj++)
                    MMA16816(C[mi][nj], afr[ks][mi], b[nj >> 1][(nj & 1) * 2],
                             b[nj >> 1][(nj & 1) * 2 + 1]);
        }

        __syncthreads();    // B buffer consumed
        if (t + 2 < ntiles) {
            copy_tile_async(smB, (const uint4*)g_h + (size_t)((ct + 2) * 128) * 16, tid);
            CP_COMMIT();
        }

        // ---- epilogue (overlaps in-flight prefetch) ----
        const int cBase0 = colBase + cOffW;
        if (isDiag) {
            #pragma unroll
            for (int mi = 0; mi < 4; mi++)
                #pragma unroll
                for (int h = 0; h < 2; h++) {
                    const int grow = rBase0 + mi * 16 + h * 8;
                    float acc = 0.0f;
                    #pragma unroll
                    for (int nj = 0; nj < 4; nj++)
                        #pragma unroll
                        for (int q = 0; q < 2; q++) {
                            const int gcol = cBase0 + nj * 8 + q;
                            const float s = C[mi][nj][h * 2 + q];
                            if (gcol != grow) acc += ex2f((s - 1.0f) * K2C);
                        }
                    racc[mi][h] += acc;
                }
        } else {
            float cacc[4][2];
            #pragma unroll
            for (int u = 0; u < 4; u++) { cacc[u][0] = 0.0f; cacc[u][1] = 0.0f; }
            #pragma unroll
            for (int mi = 0; mi < 4; mi++)
                #pragma unroll
                for (int h = 0; h < 2; h++) {
                    const int grow = rBase0 + mi * 16 + h * 8;
                    const int pcol = grow ^ (NN / 2);
                    float acc = 0.0f;
                    #pragma unroll
                    for (int nj = 0; nj < 4; nj++)
                        #pragma unroll
                        for (int q = 0; q < 2; q++) {
                            const int gcol = cBase0 + nj * 8 + q;
                            const float s = C[mi][nj][h * 2 + q];
                            const float e = ex2f((s - 1.0f) * K2C);
                            acc += e;
                            cacc[nj][q] += e;
                            if (hasPos && gcol == pcol) {
                                g_pos[grow] = s;
                                g_pos[gcol] = s;
                            }
                        }
                    racc[mi][h] += acc;
                }
            #pragma unroll
            for (int nj = 0; nj < 4; nj++)
                #pragma unroll
                for (int q = 0; q < 2; q++) {
                    float v = cacc[nj][q];
                    v += __shfl_xor_sync(0xffffffffu, v, 4);
                    v += __shfl_xor_sync(0xffffffffu, v, 8);
                    v += __shfl_xor_sync(0xffffffffu, v, 16);
                    if (lane < 4)
                        atomicAdd(&g_rowsum[cBase0 + nj * 8 + q], v);
                }
        }

        if (t + 1 < ntiles) {
            if (t + 2 < ntiles) { CP_WAIT(1); } else { CP_WAIT(0); }
            __syncthreads();
        }
    }

    // flush row accumulators
    #pragma unroll
    for (int mi = 0; mi < 4; mi++)
        #pragma unroll
        for (int h = 0; h < 2; h++) {
            float v = racc[mi][h];
            v += __shfl_xor_sync(0xffffffffu, v, 1);
            v += __shfl_xor_sync(0xffffffffu, v, 2);
            if ((lane & 3) == 0)
                atomicAdd(&g_rowsum[rBase0 + mi * 16 + h * 8], v);
        }

    // ---- fused finish: last CTA reduces the loss ----
    __threadfence();
    __syncthreads();
    if (tid == 0) lastFlag = (atomicAdd(&g_done, 1) == NGROUP - 1);
    __syncthreads();
    if (lastFlag) {
        float acc = 0.0f;
        for (int r = tid; r < NN; r += 256)
            acc += (1.0f - g_pos[r]) * (1.0f / 0.07f) + lg2f(g_rowsum[r]) * 0.69314718f;
        red[tid] = acc;
        __syncthreads();
        #pragma unroll
        for (int s = 128; s > 0; s >>= 1) {
            if (tid < s) red[tid] += red[tid + s];
            __syncthreads();
        }
        if (tid == 0) {
            out[0] = red[0] / (float)NN;
            g_done = 0;       // reset for graph replay
        }
    }
}

// ---------------------------------------------------------------------------
extern "C" void kernel_launch(void* const* d_in, const int* in_sizes, int n_in,
                              void* d_out, int out_size) {
    const float* feats = (const float*)d_in[0];
    float* out = (float*)d_out;

    cudaFuncSetAttribute(sim_kernel, cudaFuncAttributeMaxDynamicSharedMemorySize,
                         SMEM_BYTES);

    norm_kernel<<<NN / 8, 256>>>(feats);
    sim_kernel<<<NGROUP, 256, SMEM_BYTES>>>(out);
}

// round 12
// speedup vs baseline: 1.0301x; 1.0301x over previous
#include <cuda_runtime.h>
#include <cuda_fp16.h>
#include <cstdint>

#define NN 8192
#define DD 128
#define K2C 20.6099286f    // 1/(0.07*ln2)

#define NCG 128              // 64-wide column blocks
#define NGROUP 1056          // sum over rt of ceil((128-2rt)/4)
#define SMEM_BYTES 81920     // A (32KB) + B ring 3 x 16KB

// ---------------------------------------------------------------------------
__device__ uint32_t g_h[NN * 64];    // normalized feats, fp16x2
__device__ float    g_rowsum[NN];
__device__ float    g_pos[NN];
__device__ int      g_done;

__device__ __forceinline__ uint32_t smem_u32(const void* p) {
    uint32_t a;
    asm("{ .reg .u64 t; cvta.to.shared.u64 t, %1; cvt.u32.u64 %0, t; }" : "=r"(a) : "l"(p));
    return a;
}
__device__ __forceinline__ float ex2f(float x) {
    float y; asm("ex2.approx.ftz.f32 %0, %1;" : "=f"(y) : "f"(x)); return y;
}
__device__ __forceinline__ float lg2f(float x) {
    float y; asm("lg2.approx.f32 %0, %1;" : "=f"(y) : "f"(x)); return y;
}
__device__ __forceinline__ void cp16(uint32_t dst, const void* src) {
    asm volatile("cp.async.cg.shared.global [%0], [%1], 16;" :: "r"(dst), "l"(src));
}
#define CP_COMMIT() asm volatile("cp.async.commit_group;" ::: "memory")
#define CP_WAIT(n)  asm volatile("cp.async.wait_group %0;" :: "n"(n) : "memory")

#define LDSM4(r0, r1, r2, r3, a) \
    asm volatile("ldmatrix.sync.aligned.m8n8.x4.shared.b16 {%0,%1,%2,%3}, [%4];" \
                 : "=r"(r0), "=r"(r1), "=r"(r2), "=r"(r3) : "r"(a))
#define MMA16816(d, a, b0v, b1v) \
    asm volatile("mma.sync.aligned.m16n8k16.row.col.f32.f16.f16.f32 " \
                 "{%0,%1,%2,%3},{%4,%5,%6,%7},{%8,%9},{%0,%1,%2,%3};" \
                 : "+f"((d)[0]), "+f"((d)[1]), "+f"((d)[2]), "+f"((d)[3]) \
                 : "r"((a)[0]), "r"((a)[1]), "r"((a)[2]), "r"((a)[3]), \
                   "r"(b0v), "r"(b1v))

// ---------------------------------------------------------------------------
// Kernel 1: row L2-normalize -> fp16 (warp per row), zero rowsum
// ---------------------------------------------------------------------------
__global__ void norm_kernel(const float* __restrict__ feats) {
    int row  = blockIdx.x * 8 + (threadIdx.x >> 5);
    int lane = threadIdx.x & 31;
    float4 v = ((const float4*)(feats + (size_t)row * DD))[lane];
    float ss = v.x * v.x + v.y * v.y + v.z * v.z + v.w * v.w;
    #pragma unroll
    for (int o = 16; o; o >>= 1) ss += __shfl_xor_sync(0xffffffffu, ss, o);
    float inv = 1.0f / fmaxf(sqrtf(ss), 1e-8f);
    __half2 p0 = __floats2half2_rn(v.x * inv, v.y * inv);
    __half2 p1 = __floats2half2_rn(v.z * inv, v.w * inv);
    uint2 pk;
    pk.x = *(uint32_t*)&p0;
    pk.y = *(uint32_t*)&p1;
    *(uint2*)(g_h + (size_t)row * 64 + lane * 2) = pk;
    if (lane == 0) g_rowsum[row] = 0.0f;
}

// ---------------------------------------------------------------------------
// Kernel 2: 128x64 tiles, triangular (ctg >= 2rt), groups of 4, 3-deep B ring
// ---------------------------------------------------------------------------
// A tile: 128 rows x 16 chunks (32KB). B tile: 64 rows x 16 chunks (16KB).
__device__ __forceinline__ void copy_A(uint32_t smemBase,
                                       const uint4* __restrict__ src, int tid) {
    #pragma unroll
    for (int i = 0; i < 8; i++) {
        int idx = tid + i * 256;
        int r = idx >> 4, c = idx & 15;
        cp16(smemBase + (uint32_t)((r * 16 + (c ^ (r & 7))) << 4), src + idx);
    }
}
__device__ __forceinline__ void copy_B(uint32_t smemBase,
                                       const uint4* __restrict__ src, int tid) {
    #pragma unroll
    for (int i = 0; i < 4; i++) {
        int idx = tid + i * 256;
        int r = idx >> 4, c = idx & 15;
        cp16(smemBase + (uint32_t)((r * 16 + (c ^ (r & 7))) << 4), src + idx);
    }
}

__global__ void __launch_bounds__(256, 2) sim_kernel(float* __restrict__ out) {
    extern __shared__ uint4 sm4[];
    __shared__ float red[256];
    __shared__ int lastFlag;

    const int tid  = threadIdx.x;
    const int lane = tid & 31;
    const int wid  = tid >> 5;

    // decode bid -> (rt, q); groups(rt) = ceil((128-2rt)/4)
    int rt = 0, cum = 0;
    {
        const int bid = blockIdx.x;
        while (cum + ((NCG - 2 * rt + 3) >> 2) <= bid) {
            cum += (NCG - 2 * rt + 3) >> 2;
            rt++;
        }
    }
    const int q    = (int)blockIdx.x - cum;
    const int cg0  = 2 * rt + 4 * q;
    int ntiles = NCG - cg0;
    if (ntiles > 4) ntiles = 4;
    const int rowBase = rt * 128;

    const uint32_t smA = smem_u32(sm4);
    uint32_t smB[3] = { smA + 32768, smA + 32768 + 16384, smA + 32768 + 32768 };

    // prologue: group0 = A + B0 ; group1 = B1 ; group2 = B2
    copy_A(smA, (const uint4*)g_h + (size_t)rowBase * 16, tid);
    copy_B(smB[0], (const uint4*)g_h + (size_t)(cg0 * 64) * 16, tid);
    CP_COMMIT();
    if (ntiles > 1) { copy_B(smB[1], (const uint4*)g_h + (size_t)((cg0 + 1) * 64) * 16, tid); CP_COMMIT(); }
    if (ntiles > 2) { copy_B(smB[2], (const uint4*)g_h + (size_t)((cg0 + 2) * 64) * 16, tid); CP_COMMIT(); }
    if (ntiles > 2)      { CP_WAIT(2); }
    else if (ntiles > 1) { CP_WAIT(1); }
    else                 { CP_WAIT(0); }
    __syncthreads();

    const int warpM = wid & 3;          // 4 x 32 rows
    const int warpN = wid >> 2;         // 2 x 32 cols
    const int aRowL = warpM * 32 + (lane & 15);
    const int aCB   = lane >> 4;
    const int bRowL = warpN * 32 + ((lane & 7) | ((lane >> 1) & 8));
    const int bCB   = (lane >> 3) & 1;
    const int rBase0 = rowBase + warpM * 32 + (lane >> 2);
    const int cOffW  = warpN * 32 + (lane & 3) * 2;

    float racc[2][2];
    racc[0][0] = racc[0][1] = racc[1][0] = racc[1][1] = 0.0f;

    for (int t = 0; t < ntiles; t++) {
        const int cg = cg0 + t;
        const int colBase = cg * 64;
        const bool diagHalf = (cg <= 2 * rt + 1);
        const bool hasPos = (cg == 2 * rt + 64) | (cg == 2 * rt + 65);
        const uint32_t smBt = smB[t % 3];

        float C[2][4][4];
        #pragma unroll
        for (int mi = 0; mi < 2; mi++)
            #pragma unroll
            for (int nj = 0; nj < 4; nj++)
                #pragma unroll
                for (int v = 0; v < 4; v++) C[mi][nj][v] = 0.0f;

        #pragma unroll
        for (int ks = 0; ks < 8; ks++) {
            uint32_t a[2][4], b[2][4];
            #pragma unroll
            for (int mi = 0; mi < 2; mi++) {
                int r = aRowL + mi * 16;
                int ch = 2 * ks + aCB;
                LDSM4(a[mi][0], a[mi][1], a[mi][2], a[mi][3],
                      smA + r * 256 + ((ch ^ (r & 7)) << 4));
            }
            #pragma unroll
            for (int nh = 0; nh < 2; nh++) {
                int r = bRowL + nh * 16;
                int ch = 2 * ks + bCB;
                LDSM4(b[nh][0], b[nh][1], b[nh][2], b[nh][3],
                      smBt + r * 256 + ((ch ^ (r & 7)) << 4));
            }
            #pragma unroll
            for (int mi = 0; mi < 2; mi++)
                #pragma unroll
                for (int nj = 0; nj < 4; nj++)
                    MMA16816(C[mi][nj], a[mi], b[nj >> 1][(nj & 1) * 2],
                             b[nj >> 1][(nj & 1) * 2 + 1]);
        }

        __syncthreads();    // all warps done with smBt (and prior buffers)
        if (t + 3 < ntiles) {
            copy_B(smBt, (const uint4*)g_h + (size_t)((cg + 3) * 64) * 16, tid);
            CP_COMMIT();
        }

        // ---- epilogue (registers only; overlaps in-flight prefetch) ----
        const int cBase0 = colBase + cOffW;
        if (diagHalf) {
            #pragma unroll
            for (int mi = 0; mi < 2; mi++)
                #pragma unroll
                for (int h = 0; h < 2; h++) {
                    const int grow = rBase0 + mi * 16 + h * 8;
                    float acc = 0.0f;
                    #pragma unroll
                    for (int nj = 0; nj < 4; nj++)
                        #pragma unroll
                        for (int p = 0; p < 2; p++) {
                            const int gcol = cBase0 + nj * 8 + p;
                            const float s = C[mi][nj][h * 2 + p];
                            if (gcol != grow) acc += ex2f((s - 1.0f) * K2C);
                        }
                    racc[mi][h] += acc;
                }
        } else {
            float cacc[4][2];
            #pragma unroll
            for (int u = 0; u < 4; u++) { cacc[u][0] = 0.0f; cacc[u][1] = 0.0f; }
            #pragma unroll
            for (int mi = 0; mi < 2; mi++)
                #pragma unroll
                for (int h = 0; h < 2; h++) {
                    const int grow = rBase0 + mi * 16 + h * 8;
                    const int pcol = grow ^ (NN / 2);
                    float acc = 0.0f;
                    #pragma unroll
                    for (int nj = 0; nj < 4; nj++)
                        #pragma unroll
                        for (int p = 0; p < 2; p++) {
                            const int gcol = cBase0 + nj * 8 + p;
                            const float s = C[mi][nj][h * 2 + p];
                            const float e = ex2f((s - 1.0f) * K2C);
                            acc += e;
                            cacc[nj][p] += e;
                            if (hasPos && gcol == pcol) {
                                g_pos[grow] = s;
                                g_pos[gcol] = s;
                            }
                        }
                    racc[mi][h] += acc;
                }
            // column reduce: lanes with same (lane&3) share cols -> xor 4,8,16
            #pragma unroll
            for (int nj = 0; nj < 4; nj++)
                #pragma unroll
                for (int p = 0; p < 2; p++) {
                    float v = cacc[nj][p];
                    v += __shfl_xor_sync(0xffffffffu, v, 4);
                    v += __shfl_xor_sync(0xffffffffu, v, 8);
                    v += __shfl_xor_sync(0xffffffffu, v, 16);
                    if (lane < 4)
                        atomicAdd(&g_rowsum[cBase0 + nj * 8 + p], v);
                }
        }

        if (t + 1 < ntiles) {
            if (ntiles == 4) {
                if (t == 0) { CP_WAIT(2); } else if (t == 1) { CP_WAIT(1); } else { CP_WAIT(0); }
            } else if (ntiles == 3) {
                if (t == 0) { CP_WAIT(1); } else { CP_WAIT(0); }
            } else {
                CP_WAIT(0);
            }
            __syncthreads();
        }
    }

    // flush row accumulators (once per group)
    #pragma unroll
    for (int mi = 0; mi < 2; mi++)
        #pragma unroll
        for (int h = 0; h < 2; h++) {
            float v = racc[mi][h];
            v += __shfl_xor_sync(0xffffffffu, v, 1);
            v += __shfl_xor_sync(0xffffffffu, v, 2);
            if ((lane & 3) == 0)
                atomicAdd(&g_rowsum[rBase0 + mi * 16 + h * 8], v);
        }

    // ---- fused finish: last CTA reduces the loss ----
    __threadfence();
    __syncthreads();
    if (tid == 0) lastFlag = (atomicAdd(&g_done, 1) == NGROUP - 1);
    __syncthreads();
    if (lastFlag) {
        float acc = 0.0f;
        for (int r = tid; r < NN; r += 256)
            acc += (1.0f - g_pos[r]) * (1.0f / 0.07f) + lg2f(g_rowsum[r]) * 0.69314718f;
        red[tid] = acc;
        __syncthreads();
        #pragma unroll
        for (int s = 128; s > 0; s >>= 1) {
            if (tid < s) red[tid] += red[tid + s];
            __syncthreads();
        }
        if (tid == 0) {
            out[0] = red[0] / (float)NN;
            g_done = 0;       // reset for graph replay
        }
    }
}

// ---------------------------------------------------------------------------
extern "C" void kernel_launch(void* const* d_in, const int* in_sizes, int n_in,
                              void* d_out, int out_size) {
    const float* feats = (const float*)d_in[0];
    float* out = (float*)d_out;

    cudaFuncSetAttribute(sim_kernel, cudaFuncAttributeMaxDynamicSharedMemorySize,
                         SMEM_BYTES);

    norm_kernel<<<NN / 8, 256>>>(feats);
    sim_kernel<<<NGROUP, 256, SMEM_BYTES>>>(out);
}

// round 13
// speedup vs baseline: 1.2400x; 1.2038x over previous
#include <cuda_runtime.h>
#include <cuda_fp16.h>
#include <cstdint>

#define NN 8192
#define DD 128
#define K2C 20.6099286f    // 1/(0.07*ln2)

#define NTILE 64
#define NPAIR 1056
#define SMEM_BYTES 98304

// ---------------------------------------------------------------------------
__device__ uint32_t g_h[NN * 64];    // normalized feats, fp16x2
__device__ float    g_rowsum[NN];
__device__ float    g_pos[NN];
__device__ int      g_done;

__device__ __forceinline__ uint32_t smem_u32(const void* p) {
    uint32_t a;
    asm("{ .reg .u64 t; cvta.to.shared.u64 t, %1; cvt.u32.u64 %0, t; }" : "=r"(a) : "l"(p));
    return a;
}
__device__ __forceinline__ float ex2f(float x) {
    float y; asm("ex2.approx.ftz.f32 %0, %1;" : "=f"(y) : "f"(x)); return y;
}
__device__ __forceinline__ float lg2f(float x) {
    float y; asm("lg2.approx.f32 %0, %1;" : "=f"(y) : "f"(x)); return y;
}
__device__ __forceinline__ void cp16(uint32_t dst, const void* src) {
    asm volatile("cp.async.cg.shared.global [%0], [%1], 16;" :: "r"(dst), "l"(src));
}
#define CP_COMMIT() asm volatile("cp.async.commit_group;" ::: "memory")
#define CP_WAIT(n)  asm volatile("cp.async.wait_group %0;" :: "n"(n) : "memory")

#define LDSM4(r0, r1, r2, r3, a) \
    asm volatile("ldmatrix.sync.aligned.m8n8.x4.shared.b16 {%0,%1,%2,%3}, [%4];" \
                 : "=r"(r0), "=r"(r1), "=r"(r2), "=r"(r3) : "r"(a))
#define MMA16816(d, a, b0v, b1v) \
    asm volatile("mma.sync.aligned.m16n8k16.row.col.f32.f16.f16.f32 " \
                 "{%0,%1,%2,%3},{%4,%5,%6,%7},{%8,%9},{%0,%1,%2,%3};" \
                 : "+f"((d)[0]), "+f"((d)[1]), "+f"((d)[2]), "+f"((d)[3]) \
                 : "r"((a)[0]), "r"((a)[1]), "r"((a)[2]), "r"((a)[3]), \
                   "r"(b0v), "r"(b1v))

// ---------------------------------------------------------------------------
// Kernel 1: row L2-normalize -> fp16 (warp per row), zero rowsum
// ---------------------------------------------------------------------------
__global__ void norm_kernel(const float* __restrict__ feats) {
    int row  = blockIdx.x * 8 + (threadIdx.x >> 5);
    int lane = threadIdx.x & 31;
    float4 v = ((const float4*)(feats + (size_t)row * DD))[lane];
    float ss = v.x * v.x + v.y * v.y + v.z * v.z + v.w * v.w;
    #pragma unroll
    for (int o = 16; o; o >>= 1) ss += __shfl_xor_sync(0xffffffffu, ss, o);
    float inv = 1.0f / fmaxf(sqrtf(ss), 1e-8f);
    __half2 p0 = __floats2half2_rn(v.x * inv, v.y * inv);
    __half2 p1 = __floats2half2_rn(v.z * inv, v.w * inv);
    uint2 pk;
    pk.x = *(uint32_t*)&p0;
    pk.y = *(uint32_t*)&p1;
    *(uint2*)(g_h + (size_t)row * 64 + lane * 2) = pk;
    if (lane == 0) g_rowsum[row] = 0.0f;
}

// ---------------------------------------------------------------------------
// Kernel 2: triangular pair sweep (round-8 measured-best structure)
//           + fused last-CTA finish
// ---------------------------------------------------------------------------
__device__ __forceinline__ void copy_tile_async(uint32_t smemBase,
                                                const uint4* __restrict__ src,
                                                int tid) {
    #pragma unroll
    for (int i = 0; i < 8; i++) {
        int idx = tid + i * 256;
        int r = idx >> 4, c = idx & 15;
        uint32_t dst = smemBase + (uint32_t)((r * 16 + (c ^ (r & 7))) << 4);
        cp16(dst, src + idx);
    }
}

__global__ void __launch_bounds__(256, 2) sim_kernel(float* __restrict__ out) {
    extern __shared__ uint4 sm4[];
    __shared__ float red[256];
    __shared__ int lastFlag;

    const int tid  = threadIdx.x;
    const int lane = tid & 31;
    const int wid  = tid >> 5;

    // decode bid -> (rt, pairIdx); pairs(rt) = 32 - (rt>>1)
    int rt = 0, cum = 0;
    {
        const int bid = blockIdx.x;
        while (cum + (32 - (rt >> 1)) <= bid) { cum += 32 - (rt >> 1); rt++; }
    }
    const int pairIdx = (int)blockIdx.x - cum;
    const int ct0  = rt + 2 * pairIdx;
    const int numT = (ct0 + 1 < NTILE) ? 2 : 1;
    const int rowBase = rt * 128;

    const uint32_t smA  = smem_u32(sm4);
    const uint32_t smB0 = smA + 32768;
    const uint32_t smB1 = smA + 65536;

    copy_tile_async(smA, (const uint4*)g_h + (size_t)rowBase * 16, tid);
    if (ct0 != rt)
        copy_tile_async(smB0, (const uint4*)g_h + (size_t)(ct0 * 128) * 16, tid);
    CP_COMMIT();
    if (numT == 2) {
        copy_tile_async(smB1, (const uint4*)g_h + (size_t)((ct0 + 1) * 128) * 16, tid);
        CP_COMMIT();
        CP_WAIT(1);
    } else {
        CP_WAIT(0);
    }
    __syncthreads();

    const int warpM = wid & 1;
    const int warpN = wid >> 1;
    const int aRowL = warpM * 64 + (lane & 15);
    const int aCB   = lane >> 4;
    const int bRowL = warpN * 32 + ((lane & 7) | ((lane >> 1) & 8));
    const int bCB   = (lane >> 3) & 1;

    const int rBase0 = rowBase + warpM * 64 + (lane >> 2);
    const int cOffW  = warpN * 32 + (lane & 3) * 2;

    float racc[4][2];
    #pragma unroll
    for (int u = 0; u < 4; u++) { racc[u][0] = 0.0f; racc[u][1] = 0.0f; }

    for (int t = 0; t < numT; t++) {
        const int ct = ct0 + t;
        const int colBase = ct * 128;
        const bool isDiag = (ct == rt);
        const bool hasPos = (ct == rt + 32);
        const uint32_t smB = isDiag ? smA : (t == 0 ? smB0 : smB1);

        float C[4][4][4];
        #pragma unroll
        for (int mi = 0; mi < 4; mi++)
            #pragma unroll
            for (int nj = 0; nj < 4; nj++)
                #pragma unroll
                for (int q = 0; q < 4; q++) C[mi][nj][q] = 0.0f;

        #pragma unroll
        for (int ks = 0; ks < 8; ks++) {
            uint32_t a[4][4], b[2][4];
            #pragma unroll
            for (int mi = 0; mi < 4; mi++) {
                int r = aRowL + mi * 16;
                int ch = 2 * ks + aCB;
                LDSM4(a[mi][0], a[mi][1], a[mi][2], a[mi][3],
                      smA + r * 256 + ((ch ^ (r & 7)) << 4));
            }
            #pragma unroll
            for (int nh = 0; nh < 2; nh++) {
                int r = bRowL + nh * 16;
                int ch = 2 * ks + bCB;
                LDSM4(b[nh][0], b[nh][1], b[nh][2], b[nh][3],
                      smB + r * 256 + ((ch ^ (r & 7)) << 4));
            }
            #pragma unroll
            for (int mi = 0; mi < 4; mi++)
                #pragma unroll
                for (int nj = 0; nj < 4; nj++)
                    MMA16816(C[mi][nj], a[mi], b[nj >> 1][(nj & 1) * 2],
                             b[nj >> 1][(nj & 1) * 2 + 1]);
        }

        // epilogue (overlaps in-flight B1 cp.async during t==0)
        const int cBase0 = colBase + cOffW;
        if (isDiag) {
            #pragma unroll
            for (int mi = 0; mi < 4; mi++)
                #pragma unroll
                for (int h = 0; h < 2; h++) {
                    const int grow = rBase0 + mi * 16 + h * 8;
                    float acc = 0.0f;
                    #pragma unroll
                    for (int nj = 0; nj < 4; nj++)
                        #pragma unroll
                        for (int q = 0; q < 2; q++) {
                            const int gcol = cBase0 + nj * 8 + q;
                            const float s = C[mi][nj][h * 2 + q];
                            if (gcol != grow) acc += ex2f((s - 1.0f) * K2C);
                        }
                    racc[mi][h] += acc;
                }
        } else {
            float cacc[4][2];
            #pragma unroll
            for (int u = 0; u < 4; u++) { cacc[u][0] = 0.0f; cacc[u][1] = 0.0f; }

            #pragma unroll
            for (int mi = 0; mi < 4; mi++)
                #pragma unroll
                for (int h = 0; h < 2; h++) {
                    const int grow = rBase0 + mi * 16 + h * 8;
                    const int pcol = grow ^ (NN / 2);
                    float acc = 0.0f;
                    #pragma unroll
                    for (int nj = 0; nj < 4; nj++)
                        #pragma unroll
                        for (int q = 0; q < 2; q++) {
                            const int gcol = cBase0 + nj * 8 + q;
                            const float s = C[mi][nj][h * 2 + q];
                            const float e = ex2f((s - 1.0f) * K2C);
                            acc += e;
                            cacc[nj][q] += e;
                            if (hasPos && gcol == pcol) {
                                g_pos[grow] = s;
                                g_pos[gcol] = s;
                            }
                        }
                    racc[mi][h] += acc;
                }

            #pragma unroll
            for (int nj = 0; nj < 4; nj++)
                #pragma unroll
                for (int q = 0; q < 2; q++) {
                    float v = cacc[nj][q];
                    v += __shfl_xor_sync(0xffffffffu, v, 4);
                    v += __shfl_xor_sync(0xffffffffu, v, 8);
                    v += __shfl_xor_sync(0xffffffffu, v, 16);
                    if (lane < 4)
                        atomicAdd(&g_rowsum[cBase0 + nj * 8 + q], v);
                }
        }

        if (t == 0 && numT == 2) {
            CP_WAIT(0);         // B1 resident
            __syncthreads();
        }
    }

    // row reduction once for both tiles
    #pragma unroll
    for (int mi = 0; mi < 4; mi++)
        #pragma unroll
        for (int h = 0; h < 2; h++) {
            float v = racc[mi][h];
            v += __shfl_xor_sync(0xffffffffu, v, 1);
            v += __shfl_xor_sync(0xffffffffu, v, 2);
            if ((lane & 3) == 0)
                atomicAdd(&g_rowsum[rBase0 + mi * 16 + h * 8], v);
        }

    // ---- fused finish: last CTA computes the loss ----
    __threadfence();
    __syncthreads();
    if (tid == 0) lastFlag = (atomicAdd(&g_done, 1) == NPAIR - 1);
    __syncthreads();
    if (lastFlag) {
        float acc = 0.0f;
        for (int r = tid; r < NN; r += 256)
            acc += (1.0f - g_pos[r]) * (1.0f / 0.07f) + lg2f(g_rowsum[r]) * 0.69314718f;
        red[tid] = acc;
        __syncthreads();
        #pragma unroll
        for (int s = 128; s > 0; s >>= 1) {
            if (tid < s) red[tid] += red[tid + s];
            __syncthreads();
        }
        if (tid == 0) {
            out[0] = red[0] / (float)NN;
            g_done = 0;          // reset for graph replay
        }
    }
}

// ---------------------------------------------------------------------------
extern "C" void kernel_launch(void* const* d_in, const int* in_sizes, int n_in,
                              void* d_out, int out_size) {
    const float* feats = (const float*)d_in[0];
    float* out = (float*)d_out;

    cudaFuncSetAttribute(sim_kernel, cudaFuncAttributeMaxDynamicSharedMemorySize,
                         SMEM_BYTES);

    norm_kernel<<<NN / 8, 256>>>(feats);
    sim_kernel<<<NPAIR, 256, SMEM_BYTES>>>(out);
}

// round 14
// speedup vs baseline: 1.2408x; 1.0006x over previous
#include <cuda_runtime.h>
#include <cuda_fp16.h>
#include <cstdint>

#define NN 8192
#define DD 128
#define K2C 20.6099286f    // 1/(0.07*ln2)

#define NTILE 64
#define NPAIR 1056
#define SMEM_BYTES 98304

// ---------------------------------------------------------------------------
__device__ uint32_t g_h[NN * 64];    // normalized feats, fp16x2
__device__ float    g_rowsum[NN];
__device__ float    g_pos[NN];

__device__ __forceinline__ uint32_t smem_u32(const void* p) {
    uint32_t a;
    asm("{ .reg .u64 t; cvta.to.shared.u64 t, %1; cvt.u32.u64 %0, t; }" : "=r"(a) : "l"(p));
    return a;
}
__device__ __forceinline__ float ex2f(float x) {
    float y; asm("ex2.approx.ftz.f32 %0, %1;" : "=f"(y) : "f"(x)); return y;
}
__device__ __forceinline__ float lg2f(float x) {
    float y; asm("lg2.approx.f32 %0, %1;" : "=f"(y) : "f"(x)); return y;
}
__device__ __forceinline__ void cp16(uint32_t dst, const void* src) {
    asm volatile("cp.async.cg.shared.global [%0], [%1], 16;" :: "r"(dst), "l"(src));
}
#define CP_COMMIT() asm volatile("cp.async.commit_group;" ::: "memory")
#define CP_WAIT(n)  asm volatile("cp.async.wait_group %0;" :: "n"(n) : "memory")

#define LDSM4(r0, r1, r2, r3, a) \
    asm volatile("ldmatrix.sync.aligned.m8n8.x4.shared.b16 {%0,%1,%2,%3}, [%4];" \
                 : "=r"(r0), "=r"(r1), "=r"(r2), "=r"(r3) : "r"(a))
#define MMA16816(d, a, b0v, b1v) \
    asm volatile("mma.sync.aligned.m16n8k16.row.col.f32.f16.f16.f32 " \
                 "{%0,%1,%2,%3},{%4,%5,%6,%7},{%8,%9},{%0,%1,%2,%3};" \
                 : "+f"((d)[0]), "+f"((d)[1]), "+f"((d)[2]), "+f"((d)[3]) \
                 : "r"((a)[0]), "r"((a)[1]), "r"((a)[2]), "r"((a)[3]), \
                   "r"(b0v), "r"(b1v))

// ---------------------------------------------------------------------------
// Kernel 1: row L2-normalize -> fp16 (warp per row), zero rowsum
// ---------------------------------------------------------------------------
__global__ void norm_kernel(const float* __restrict__ feats) {
    int row  = blockIdx.x * 8 + (threadIdx.x >> 5);
    int lane = threadIdx.x & 31;
    float4 v = ((const float4*)(feats + (size_t)row * DD))[lane];
    float ss = v.x * v.x + v.y * v.y + v.z * v.z + v.w * v.w;
    #pragma unroll
    for (int o = 16; o; o >>= 1) ss += __shfl_xor_sync(0xffffffffu, ss, o);
    float inv = 1.0f / fmaxf(sqrtf(ss), 1e-8f);
    __half2 p0 = __floats2half2_rn(v.x * inv, v.y * inv);
    __half2 p1 = __floats2half2_rn(v.z * inv, v.w * inv);
    uint2 pk;
    pk.x = *(uint32_t*)&p0;
    pk.y = *(uint32_t*)&p1;
    *(uint2*)(g_h + (size_t)row * 64 + lane * 2) = pk;
    if (lane == 0) g_rowsum[row] = 0.0f;
}

// ---------------------------------------------------------------------------
// Kernel 2: triangular pair sweep; row-split mainloop with interleaved
//           half-epilogue (MUFU hidden under HMMA); branchless epilogue.
// ---------------------------------------------------------------------------
__device__ __forceinline__ void copy_tile_async(uint32_t smemBase,
                                                const uint4* __restrict__ src,
                                                int tid) {
    #pragma unroll
    for (int i = 0; i < 8; i++) {
        int idx = tid + i * 256;
        int r = idx >> 4, c = idx & 15;
        uint32_t dst = smemBase + (uint32_t)((r * 16 + (c ^ (r & 7))) << 4);
        cp16(dst, src + idx);
    }
}

__global__ void __launch_bounds__(256, 2) sim_kernel() {
    extern __shared__ uint4 sm4[];
    const int tid  = threadIdx.x;
    const int lane = tid & 31;
    const int wid  = tid >> 5;

    // decode bid -> (rt, pairIdx); pairs(rt) = 32 - (rt>>1)
    int rt = 0, cum = 0;
    {
        const int bid = blockIdx.x;
        while (cum + (32 - (rt >> 1)) <= bid) { cum += 32 - (rt >> 1); rt++; }
    }
    const int pairIdx = (int)blockIdx.x - cum;
    const int ct0  = rt + 2 * pairIdx;
    const int numT = (ct0 + 1 < NTILE) ? 2 : 1;
    const int rowBase = rt * 128;

    const uint32_t smA  = smem_u32(sm4);
    const uint32_t smB0 = smA + 32768;
    const uint32_t smB1 = smA + 65536;

    copy_tile_async(smA, (const uint4*)g_h + (size_t)rowBase * 16, tid);
    if (ct0 != rt)
        copy_tile_async(smB0, (const uint4*)g_h + (size_t)(ct0 * 128) * 16, tid);
    CP_COMMIT();
    if (numT == 2) {
        copy_tile_async(smB1, (const uint4*)g_h + (size_t)((ct0 + 1) * 128) * 16, tid);
        CP_COMMIT();
        CP_WAIT(1);
    } else {
        CP_WAIT(0);
    }
    __syncthreads();

    const int warpM = wid & 1;
    const int warpN = wid >> 1;
    const int aRowL = warpM * 64 + (lane & 15);
    const int aCB   = lane >> 4;
    const int bRowL = warpN * 32 + ((lane & 7) | ((lane >> 1) & 8));
    const int bCB   = (lane >> 3) & 1;

    const int rBase0 = rowBase + warpM * 64 + (lane >> 2);
    const int cOffW  = warpN * 32 + (lane & 3) * 2;

    float racc[4][2];
    #pragma unroll
    for (int u = 0; u < 4; u++) { racc[u][0] = 0.0f; racc[u][1] = 0.0f; }

    for (int t = 0; t < numT; t++) {
        const int ct = ct0 + t;
        const int colBase = ct * 128;
        const bool isDiag = (ct == rt);
        const int hasPos = (ct == rt + 32) ? 1 : 0;
        const uint32_t smB = isDiag ? smA : (t == 0 ? smB0 : smB1);
        const int cBase0 = colBase + cOffW;

        float C[4][4][4];
        #pragma unroll
        for (int mi = 0; mi < 4; mi++)
            #pragma unroll
            for (int nj = 0; nj < 4; nj++)
                #pragma unroll
                for (int q = 0; q < 4; q++) C[mi][nj][q] = 0.0f;

        float cacc[4][2];
        #pragma unroll
        for (int u = 0; u < 4; u++) { cacc[u][0] = 0.0f; cacc[u][1] = 0.0f; }

        // ==== subloop A: rows mi 0..1 ====
        #pragma unroll
        for (int ks = 0; ks < 8; ks++) {
            uint32_t a[2][4], b[2][4];
            #pragma unroll
            for (int mi = 0; mi < 2; mi++) {
                int r = aRowL + mi * 16;
                int ch = 2 * ks + aCB;
                LDSM4(a[mi][0], a[mi][1], a[mi][2], a[mi][3],
                      smA + r * 256 + ((ch ^ (r & 7)) << 4));
            }
            #pragma unroll
            for (int nh = 0; nh < 2; nh++) {
                int r = bRowL + nh * 16;
                int ch = 2 * ks + bCB;
                LDSM4(b[nh][0], b[nh][1], b[nh][2], b[nh][3],
                      smB + r * 256 + ((ch ^ (r & 7)) << 4));
            }
            #pragma unroll
            for (int mi = 0; mi < 2; mi++)
                #pragma unroll
                for (int nj = 0; nj < 4; nj++)
                    MMA16816(C[mi][nj], a[mi], b[nj >> 1][(nj & 1) * 2],
                             b[nj >> 1][(nj & 1) * 2 + 1]);
        }

        // ==== epilogue A (rows 0..1) — branchless; overlaps subloop B ====
        #pragma unroll
        for (int mi = 0; mi < 2; mi++)
            #pragma unroll
            for (int h = 0; h < 2; h++) {
                const int grow = rBase0 + mi * 16 + h * 8;
                const int pcol = grow ^ (NN / 2);
                float acc = 0.0f;
                #pragma unroll
                for (int nj = 0; nj < 4; nj++)
                    #pragma unroll
                    for (int q = 0; q < 2; q++) {
                        const int gcol = cBase0 + nj * 8 + q;
                        const float s = C[mi][nj][h * 2 + q];
                        float e = ex2f(fmaf(s, K2C, -K2C));
                        e = (gcol != grow) ? e : 0.0f;
                        acc += e;
                        cacc[nj][q] += e;
                        if (hasPos & (gcol == pcol)) {
                            g_pos[grow] = s;
                            g_pos[gcol] = s;
                        }
                    }
                racc[mi][h] += acc;
            }

        // ==== subloop B: rows mi 2..3 ====
        #pragma unroll
        for (int ks = 0; ks < 8; ks++) {
            uint32_t a[2][4], b[2][4];
            #pragma unroll
            for (int mi = 0; mi < 2; mi++) {
                int r = aRowL + (mi + 2) * 16;
                int ch = 2 * ks + aCB;
                LDSM4(a[mi][0], a[mi][1], a[mi][2], a[mi][3],
                      smA + r * 256 + ((ch ^ (r & 7)) << 4));
            }
            #pragma unroll
            for (int nh = 0; nh < 2; nh++) {
                int r = bRowL + nh * 16;
                int ch = 2 * ks + bCB;
                LDSM4(b[nh][0], b[nh][1], b[nh][2], b[nh][3],
                      smB + r * 256 + ((ch ^ (r & 7)) << 4));
            }
            #pragma unroll
            for (int mi = 0; mi < 2; mi++)
                #pragma unroll
                for (int nj = 0; nj < 4; nj++)
                    MMA16816(C[mi + 2][nj], a[mi], b[nj >> 1][(nj & 1) * 2],
                             b[nj >> 1][(nj & 1) * 2 + 1]);
        }

        // ==== epilogue B (rows 2..3) ====
        #pragma unroll
        for (int mi = 2; mi < 4; mi++)
            #pragma unroll
            for (int h = 0; h < 2; h++) {
                const int grow = rBase0 + mi * 16 + h * 8;
                const int pcol = grow ^ (NN / 2);
                float acc = 0.0f;
                #pragma unroll
                for (int nj = 0; nj < 4; nj++)
                    #pragma unroll
                    for (int q = 0; q < 2; q++) {
                        const int gcol = cBase0 + nj * 8 + q;
                        const float s = C[mi][nj][h * 2 + q];
                        float e = ex2f(fmaf(s, K2C, -K2C));
                        e = (gcol != grow) ? e : 0.0f;
                        acc += e;
                        cacc[nj][q] += e;
                        if (hasPos & (gcol == pcol)) {
                            g_pos[grow] = s;
                            g_pos[gcol] = s;
                        }
                    }
                racc[mi][h] += acc;
            }

        // column flush (skip for diag tiles: rows already cover everything)
        if (!isDiag) {
            #pragma unroll
            for (int nj = 0; nj < 4; nj++)
                #pragma unroll
                for (int q = 0; q < 2; q++) {
                    float v = cacc[nj][q];
                    v += __shfl_xor_sync(0xffffffffu, v, 4);
                    v += __shfl_xor_sync(0xffffffffu, v, 8);
                    v += __shfl_xor_sync(0xffffffffu, v, 16);
                    if (lane < 4)
                        atomicAdd(&g_rowsum[cBase0 + nj * 8 + q], v);
                }
        }

        if (t == 0 && numT == 2) {
            CP_WAIT(0);         // B1 resident
            __syncthreads();
        }
    }

    // row reduction once for both tiles
    #pragma unroll
    for (int mi = 0; mi < 4; mi++)
        #pragma unroll
        for (int h = 0; h < 2; h++) {
            float v = racc[mi][h];
            v += __shfl_xor_sync(0xffffffffu, v, 1);
            v += __shfl_xor_sync(0xffffffffu, v, 2);
            if ((lane & 3) == 0)
                atomicAdd(&g_rowsum[rBase0 + mi * 16 + h * 8], v);
        }
}

// ---------------------------------------------------------------------------
// Kernel 3: loss = mean( (1 - pos)/T + ln(rowsum) )
// ---------------------------------------------------------------------------
__global__ void finish_kernel(float* __restrict__ out) {
    __shared__ float red[1024];
    const int tid = threadIdx.x;
    float acc = 0.0f;
    for (int r = tid; r < NN; r += 1024)
        acc += (1.0f - g_pos[r]) * (1.0f / 0.07f) + lg2f(g_rowsum[r]) * 0.69314718f;
    red[tid] = acc;
    __syncthreads();
    #pragma unroll
    for (int s = 512; s > 0; s >>= 1) {
        if (tid < s) red[tid] += red[tid + s];
        __syncthreads();
    }
    if (tid == 0) out[0] = red[0] / (float)NN;
}

// ---------------------------------------------------------------------------
extern "C" void kernel_launch(void* const* d_in, const int* in_sizes, int n_in,
                              void* d_out, int out_size) {
    const float* feats = (const float*)d_in[0];
    float* out = (float*)d_out;

    cudaFuncSetAttribute(sim_kernel, cudaFuncAttributeMaxDynamicSharedMemorySize,
                         SMEM_BYTES);

    norm_kernel<<<NN / 8, 256>>>(feats);
    sim_kernel<<<NPAIR, 256, SMEM_BYTES>>>();
    finish_kernel<<<1, 1024>>>(out);
}

// round 15
// speedup vs baseline: 1.4091x; 1.1357x over previous
#include <cuda_runtime.h>
#include <cuda_fp16.h>
#include <cstdint>

#define NN 8192
#define DD 128
#define K2C 20.6099286f    // 1/(0.07*ln2)

#define NTILE 64
#define NPAIR 1056
#define SMEM_BYTES 98304

// ---------------------------------------------------------------------------
__device__ uint32_t g_h[NN * 64];    // normalized feats, fp16x2
__device__ float    g_rowsum[NN];
__device__ float    g_pos[NN];

__device__ __forceinline__ uint32_t smem_u32(const void* p) {
    uint32_t a;
    asm("{ .reg .u64 t; cvta.to.shared.u64 t, %1; cvt.u32.u64 %0, t; }" : "=r"(a) : "l"(p));
    return a;
}
__device__ __forceinline__ float ex2f(float x) {
    float y; asm("ex2.approx.ftz.f32 %0, %1;" : "=f"(y) : "f"(x)); return y;
}
__device__ __forceinline__ float lg2f(float x) {
    float y; asm("lg2.approx.f32 %0, %1;" : "=f"(y) : "f"(x)); return y;
}
__device__ __forceinline__ void cp16(uint32_t dst, const void* src) {
    asm volatile("cp.async.cg.shared.global [%0], [%1], 16;" :: "r"(dst), "l"(src));
}
#define CP_COMMIT() asm volatile("cp.async.commit_group;" ::: "memory")
#define CP_WAIT(n)  asm volatile("cp.async.wait_group %0;" :: "n"(n) : "memory")

#define LDSM4(r0, r1, r2, r3, a) \
    asm volatile("ldmatrix.sync.aligned.m8n8.x4.shared.b16 {%0,%1,%2,%3}, [%4];" \
                 : "=r"(r0), "=r"(r1), "=r"(r2), "=r"(r3) : "r"(a))
#define MMA16816(d, a, b0v, b1v) \
    asm volatile("mma.sync.aligned.m16n8k16.row.col.f32.f16.f16.f32 " \
                 "{%0,%1,%2,%3},{%4,%5,%6,%7},{%8,%9},{%0,%1,%2,%3};" \
                 : "+f"((d)[0]), "+f"((d)[1]), "+f"((d)[2]), "+f"((d)[3]) \
                 : "r"((a)[0]), "r"((a)[1]), "r"((a)[2]), "r"((a)[3]), \
                   "r"(b0v), "r"(b1v))

// ---------------------------------------------------------------------------
// Kernel 1: row L2-normalize -> fp16 (warp per row), zero rowsum
// ---------------------------------------------------------------------------
__global__ void norm_kernel(const float* __restrict__ feats) {
    int row  = blockIdx.x * 8 + (threadIdx.x >> 5);
    int lane = threadIdx.x & 31;
    float4 v = ((const float4*)(feats + (size_t)row * DD))[lane];
    float ss = v.x * v.x + v.y * v.y + v.z * v.z + v.w * v.w;
    #pragma unroll
    for (int o = 16; o; o >>= 1) ss += __shfl_xor_sync(0xffffffffu, ss, o);
    float inv = 1.0f / fmaxf(sqrtf(ss), 1e-8f);
    __half2 p0 = __floats2half2_rn(v.x * inv, v.y * inv);
    __half2 p1 = __floats2half2_rn(v.z * inv, v.w * inv);
    uint2 pk;
    pk.x = *(uint32_t*)&p0;
    pk.y = *(uint32_t*)&p1;
    *(uint2*)(g_h + (size_t)row * 64 + lane * 2) = pk;
    if (lane == 0) g_rowsum[row] = 0.0f;
}

// ---------------------------------------------------------------------------
// Kernel 2: triangular pair sweep (R8 structure) with NO inter-tile barrier:
//   both B tiles resident after the single prologue sync; warps free-run
//   across main0/epi0/main1/epi1 so MUFU epilogues overlap HMMA mainloops
//   of skewed warps.
// ---------------------------------------------------------------------------
__device__ __forceinline__ void copy_tile_async(uint32_t smemBase,
                                                const uint4* __restrict__ src,
                                                int tid) {
    #pragma unroll
    for (int i = 0; i < 8; i++) {
        int idx = tid + i * 256;
        int r = idx >> 4, c = idx & 15;
        uint32_t dst = smemBase + (uint32_t)((r * 16 + (c ^ (r & 7))) << 4);
        cp16(dst, src + idx);
    }
}

__global__ void __launch_bounds__(256, 2) sim_kernel() {
    extern __shared__ uint4 sm4[];
    const int tid  = threadIdx.x;
    const int lane = tid & 31;
    const int wid  = tid >> 5;

    // decode bid -> (rt, pairIdx); pairs(rt) = 32 - (rt>>1)
    int rt = 0, cum = 0;
    {
        const int bid = blockIdx.x;
        while (cum + (32 - (rt >> 1)) <= bid) { cum += 32 - (rt >> 1); rt++; }
    }
    const int pairIdx = (int)blockIdx.x - cum;
    const int ct0  = rt + 2 * pairIdx;
    const int numT = (ct0 + 1 < NTILE) ? 2 : 1;
    const int rowBase = rt * 128;

    const uint32_t smA  = smem_u32(sm4);
    const uint32_t smB0 = smA + 32768;
    const uint32_t smB1 = smA + 65536;

    // prologue: load A, B0, B1; ONE wait + ONE barrier; no syncs afterwards
    copy_tile_async(smA, (const uint4*)g_h + (size_t)rowBase * 16, tid);
    if (ct0 != rt)
        copy_tile_async(smB0, (const uint4*)g_h + (size_t)(ct0 * 128) * 16, tid);
    if (numT == 2)
        copy_tile_async(smB1, (const uint4*)g_h + (size_t)((ct0 + 1) * 128) * 16, tid);
    CP_COMMIT();
    CP_WAIT(0);
    __syncthreads();

    const int warpM = wid & 1;
    const int warpN = wid >> 1;
    const int aRowL = warpM * 64 + (lane & 15);
    const int aCB   = lane >> 4;
    const int bRowL = warpN * 32 + ((lane & 7) | ((lane >> 1) & 8));
    const int bCB   = (lane >> 3) & 1;

    const int rBase0 = rowBase + warpM * 64 + (lane >> 2);
    const int cOffW  = warpN * 32 + (lane & 3) * 2;

    float racc[4][2];
    #pragma unroll
    for (int u = 0; u < 4; u++) { racc[u][0] = 0.0f; racc[u][1] = 0.0f; }

    for (int t = 0; t < numT; t++) {
        const int ct = ct0 + t;
        const int colBase = ct * 128;
        const bool isDiag = (ct == rt);
        const bool hasPos = (ct == rt + 32);
        const uint32_t smB = isDiag ? smA : (t == 0 ? smB0 : smB1);

        float C[4][4][4];
        #pragma unroll
        for (int mi = 0; mi < 4; mi++)
            #pragma unroll
            for (int nj = 0; nj < 4; nj++)
                #pragma unroll
                for (int q = 0; q < 4; q++) C[mi][nj][q] = 0.0f;

        #pragma unroll
        for (int ks = 0; ks < 8; ks++) {
            uint32_t a[4][4], b[2][4];
            #pragma unroll
            for (int mi = 0; mi < 4; mi++) {
                int r = aRowL + mi * 16;
                int ch = 2 * ks + aCB;
                LDSM4(a[mi][0], a[mi][1], a[mi][2], a[mi][3],
                      smA + r * 256 + ((ch ^ (r & 7)) << 4));
            }
            #pragma unroll
            for (int nh = 0; nh < 2; nh++) {
                int r = bRowL + nh * 16;
                int ch = 2 * ks + bCB;
                LDSM4(b[nh][0], b[nh][1], b[nh][2], b[nh][3],
                      smB + r * 256 + ((ch ^ (r & 7)) << 4));
            }
            #pragma unroll
            for (int mi = 0; mi < 4; mi++)
                #pragma unroll
                for (int nj = 0; nj < 4; nj++)
                    MMA16816(C[mi][nj], a[mi], b[nj >> 1][(nj & 1) * 2],
                             b[nj >> 1][(nj & 1) * 2 + 1]);
        }

        // ---- epilogue (no barrier before or after) ----
        const int cBase0 = colBase + cOffW;
        if (isDiag) {
            #pragma unroll
            for (int mi = 0; mi < 4; mi++)
                #pragma unroll
                for (int h = 0; h < 2; h++) {
                    const int grow = rBase0 + mi * 16 + h * 8;
                    float acc = 0.0f;
                    #pragma unroll
                    for (int nj = 0; nj < 4; nj++)
                        #pragma unroll
                        for (int q = 0; q < 2; q++) {
                            const int gcol = cBase0 + nj * 8 + q;
                            const float s = C[mi][nj][h * 2 + q];
                            if (gcol != grow) acc += ex2f(fmaf(s, K2C, -K2C));
                        }
                    racc[mi][h] += acc;
                }
        } else {
            float cacc[4][2];
            #pragma unroll
            for (int u = 0; u < 4; u++) { cacc[u][0] = 0.0f; cacc[u][1] = 0.0f; }

            #pragma unroll
            for (int mi = 0; mi < 4; mi++)
                #pragma unroll
                for (int h = 0; h < 2; h++) {
                    const int grow = rBase0 + mi * 16 + h * 8;
                    const int pcol = grow ^ (NN / 2);
                    float acc = 0.0f;
                    #pragma unroll
                    for (int nj = 0; nj < 4; nj++)
                        #pragma unroll
                        for (int q = 0; q < 2; q++) {
                            const int gcol = cBase0 + nj * 8 + q;
                            const float s = C[mi][nj][h * 2 + q];
                            const float e = ex2f(fmaf(s, K2C, -K2C));
                            acc += e;
                            cacc[nj][q] += e;
                            if (hasPos && gcol == pcol) {
                                g_pos[grow] = s;
                                g_pos[gcol] = s;
                            }
                        }
                    racc[mi][h] += acc;
                }

            #pragma unroll
            for (int nj = 0; nj < 4; nj++)
                #pragma unroll
                for (int q = 0; q < 2; q++) {
                    float v = cacc[nj][q];
                    v += __shfl_xor_sync(0xffffffffu, v, 4);
                    v += __shfl_xor_sync(0xffffffffu, v, 8);
                    v += __shfl_xor_sync(0xffffffffu, v, 16);
                    if (lane < 4)
                        atomicAdd(&g_rowsum[cBase0 + nj * 8 + q], v);
                }
        }
    }

    // row reduction once for both tiles
    #pragma unroll
    for (int mi = 0; mi < 4; mi++)
        #pragma unroll
        for (int h = 0; h < 2; h++) {
            float v = racc[mi][h];
            v += __shfl_xor_sync(0xffffffffu, v, 1);
            v += __shfl_xor_sync(0xffffffffu, v, 2);
            if ((lane & 3) == 0)
                atomicAdd(&g_rowsum[rBase0 + mi * 16 + h * 8], v);
        }
}

// ---------------------------------------------------------------------------
// Kernel 3: loss = mean( (1 - pos)/T + ln(rowsum) )
// ---------------------------------------------------------------------------
__global__ void finish_kernel(float* __restrict__ out) {
    __shared__ float red[1024];
    const int tid = threadIdx.x;
    float acc = 0.0f;
    for (int r = tid; r < NN; r += 1024)
        acc += (1.0f - g_pos[r]) * (1.0f / 0.07f) + lg2f(g_rowsum[r]) * 0.69314718f;
    red[tid] = acc;
    __syncthreads();
    #pragma unroll
    for (int s = 512; s > 0; s >>= 1) {
        if (tid < s) red[tid] += red[tid + s];
        __syncthreads();
    }
    if (tid == 0) out[0] = red[0] / (float)NN;
}

// ---------------------------------------------------------------------------
extern "C" void kernel_launch(void* const* d_in, const int* in_sizes, int n_in,
                              void* d_out, int out_size) {
    const float* feats = (const float*)d_in[0];
    float* out = (float*)d_out;

    cudaFuncSetAttribute(sim_kernel, cudaFuncAttributeMaxDynamicSharedMemorySize,
                         SMEM_BYTES);

    norm_kernel<<<NN / 8, 256>>>(feats);
    sim_kernel<<<NPAIR, 256, SMEM_BYTES>>>();
    finish_kernel<<<1, 1024>>>(out);
}